// round 14
// baseline (speedup 1.0000x reference)
#include <cuda_runtime.h>
#include <cuda_bf16.h>
#include <math.h>

// Problem dims (fixed by dataset)
#define BB 64
#define SS 512
#define HH 768
#define LL 9

#define SPLIT 8                 // chunk lanes per token
#define HC (HH / SPLIT)         // 96 features per chunk
#define NQ (HH / 32)            // 24 stages (32 features each, 4 rows per chunk-lane)
#define WREG (NQ * LL * 4 + 4)  // 868 floats per chunk region; 868 mod 32 = 4 (bank rotation)

// Chunk c owns global rows { q*32 + c*4 + j : q in [0,24), j in [0,4) }.
// x load at stage q: float4 index q*8+c -> 8 chunk lanes read one 128B line.
// W staged as per-(stage,col) quads: Ws[c*WREG + (q*9+l)*4 + j] = W[(q*32+c*4+j)*9 + l]
// -> one LDS.128 gives two b64 pairs matching the x float4's natural pairs,
//    feeding packed fma.rn.f32x2 with ZERO pack/unpack instructions.

// Scratch (no device allocations allowed)
__device__ int g_cnt[BB];        // valid count per batch
__device__ int g_src[BB * SS];   // per-batch: src token index for dest d

// packed f32x2 FMA: d = a*b + d (elementwise on the two f32 lanes)
#define FMA2(d, a, b) asm("fma.rn.f32x2 %0, %1, %2, %0;" : "+l"(d) : "l"(a), "l"(b))
#define UNPACK2(lo, hi, v) asm("mov.b64 {%0, %1}, %2;" : "=f"(lo), "=f"(hi) : "l"(v))

// ---------------------------------------------------------------------------
// Kernel A: warp-per-batch ballot scan of valid_mask -> src map + counts.
// ---------------------------------------------------------------------------
__global__ __launch_bounds__(1024) void scan_kernel(const int* __restrict__ mask) {
    int warp = (blockIdx.x * 1024 + threadIdx.x) >> 5;   // 0..63 = batch
    int lane = threadIdx.x & 31;
    if (warp >= BB) return;
    const int* mrow = mask + warp * SS;
    int base = 0;
#pragma unroll
    for (int it = 0; it < SS / 32; it++) {
        int s = it * 32 + lane;
        int m = (mrow[s] == 1) ? 1 : 0;
        unsigned bits = __ballot_sync(0xffffffffu, m);
        if (m) g_src[warp * SS + base + __popc(bits & ((1u << lane) - 1u))] = s;
        base += __popc(bits);
    }
    if (lane == 0) g_cnt[warp] = base;
}

// ---------------------------------------------------------------------------
// Kernel B: main compute + item mapping + tail fill.
// 8 chunk-lanes x 4 token-lanes, 2 tokens/lane sharing W LDS loads; packed
// f32x2 FMA over row-pairs (lo = rows 4q+{0,1}, hi = rows 4q+{2,3}).
// ---------------------------------------------------------------------------
#define NBLK 296

__global__ __launch_bounds__(256, 2) void main_kernel(const float* __restrict__ seq,
                                                      const float* __restrict__ W,
                                                      const float* __restrict__ bias,
                                                      float* __restrict__ out) {
    __shared__ float Ws[SPLIT * WREG];    // ~27.8 KB, quad-of-rows per (stage,col)
    __shared__ float Bs[LL];
    __shared__ int praw[BB];
    __shared__ int pref[BB + 1];          // pref[b] = sum cnt[0..b-1]; pref[BB]=total
    __shared__ int sitem[8][8];           // per-warp staged items

    int tid = threadIdx.x;
    if (tid < LL) Bs[tid] = bias[tid];
    if (tid < BB) praw[tid] = g_cnt[tid];
    // W preamble: region c, offset (q*9+l)*4 + j  <-  W[(q*32 + c*4 + j)*9 + l]
    for (int i = tid; i < SPLIT * WREG; i += 256) {
        int c = i / WREG, r = i % WREG;
        float val = 0.f;
        if (r < NQ * LL * 4) {
            int quad = r >> 2;          // q*9 + l
            int j = r & 3;
            int q = quad / LL, l = quad % LL;
            int g = q * 32 + c * 4 + j;
            val = W[g * LL + l];
        }
        Ws[i] = val;
    }
    __syncthreads();

    // warp-parallel exclusive prefix over 64 counts (warp 0 only)
    if (tid < 32) {
        int v0 = praw[tid];
        int v1 = praw[32 + tid];
#pragma unroll
        for (int o = 1; o < 32; o <<= 1) {
            int t0 = __shfl_up_sync(0xffffffffu, v0, o);
            int t1 = __shfl_up_sync(0xffffffffu, v1, o);
            if (tid >= o) { v0 += t0; v1 += t1; }
        }
        int sum0 = __shfl_sync(0xffffffffu, v0, 31);
        v1 += sum0;
        pref[tid + 1] = v0;
        pref[tid + 33] = v1;
        if (tid == 0) pref[0] = 0;
    }
    __syncthreads();

    int total = pref[BB];
    int n_sg = (total + 7) >> 3;   // supergroups of 8 work items

    int wid = tid >> 5, lane = tid & 31;
    int t_in = lane >> 3;   // token-lane 0..3
    int c    = lane & 7;    // chunk 0..7
    int wbase = c * WREG;

    int warp_g = blockIdx.x * 8 + wid;
    int nwarps = NBLK * 8;

    for (int sg = warp_g; sg < n_sg; sg += nwarps) {
        // ---- item mapping: lanes 0..7 search; results via smem ----
        int ii = sg * 8 + lane;
        if (lane < 8) {
            int q = (ii < total) ? ii : (total - 1);
            int b = 0;
#pragma unroll
            for (int st = 32; st >= 1; st >>= 1) {
                int mb = b + st;
                if (mb <= BB - 1 && pref[mb] <= q) b = mb;
            }
            int d = q - pref[b];
            int s = g_src[b * SS + d];
            sitem[wid][lane] = (b << 18) | (d << 9) | s;
        }
        __syncwarp();

        int i1 = sg * 8 + t_in;
        int i2 = i1 + 4;
        bool a1 = i1 < total;
        bool a2 = i2 < total;
        int item1 = sitem[wid][t_in];
        int item2 = sitem[wid][t_in + 4];
        int b1 = item1 >> 18, d1 = (item1 >> 9) & 511, s1 = item1 & 511;
        int b2 = item2 >> 18, d2 = (item2 >> 9) & 511, s2 = item2 & 511;

        const ulonglong2* xp1 = (const ulonglong2*)(seq + (size_t)(b1 * SS + s1) * HH);
        const ulonglong2* xp2 = (const ulonglong2*)(seq + (size_t)(b2 * SS + s2) * HH);

        // packed accumulators: lo = rows 4q+{0,1}, hi = rows 4q+{2,3} partials
        unsigned long long accP1[LL], accP2[LL];
#pragma unroll
        for (int l = 0; l < LL; l++) { accP1[l] = 0ull; accP2[l] = 0ull; }

        ulonglong2 A1, A2, B1, B2;

#define CONSUME(X1, X2, Q)                                                     \
        {                                                                      \
            _Pragma("unroll") for (int l = 0; l < LL; l++) {                   \
                ulonglong2 wq = *(const ulonglong2*)&Ws[wbase + ((Q) * LL + l) * 4]; \
                FMA2(accP1[l], X1.x, wq.x);                                    \
                FMA2(accP1[l], X1.y, wq.y);                                    \
                FMA2(accP2[l], X2.x, wq.x);                                    \
                FMA2(accP2[l], X2.y, wq.y);                                    \
            }                                                                  \
        }

        // stage q: this lane reads 16B index q*8 + c (coalesced per token)
        A1 = xp1[c]; A2 = xp2[c];
#pragma unroll
        for (int q = 0; q < NQ; q += 2) {
            B1 = xp1[(q + 1) * 8 + c]; B2 = xp2[(q + 1) * 8 + c];
            CONSUME(A1, A2, q);
            if (q + 2 < NQ) { A1 = xp1[(q + 2) * 8 + c]; A2 = xp2[(q + 2) * 8 + c]; }
            CONSUME(B1, B2, q + 1);
        }
#undef CONSUME

        // fold packed lanes, then reduce over the 8 chunk lanes (xor 1,2,4)
        float acc1[LL], acc2[LL];
#pragma unroll
        for (int l = 0; l < LL; l++) {
            float lo, hi;
            UNPACK2(lo, hi, accP1[l]); acc1[l] = lo + hi;
            UNPACK2(lo, hi, accP2[l]); acc2[l] = lo + hi;
        }
#pragma unroll
        for (int o = 1; o <= 4; o <<= 1) {
#pragma unroll
            for (int l = 0; l < LL; l++) {
                acc1[l] += __shfl_xor_sync(0xffffffffu, acc1[l], o);
                acc2[l] += __shfl_xor_sync(0xffffffffu, acc2[l], o);
            }
        }

        bool doit = (c == 0) ? a1 : ((c == 1) ? a2 : false);
        if (doit) {
            float v[LL];
            int slot;
            if (c == 0) {
#pragma unroll
                for (int l = 0; l < LL; l++) v[l] = acc1[l] + Bs[l];
                slot = b1 * SS + d1;
            } else {
#pragma unroll
                for (int l = 0; l < LL; l++) v[l] = acc2[l] + Bs[l];
                slot = b2 * SS + d2;
            }
            float m = v[0];
#pragma unroll
            for (int l = 1; l < LL; l++) m = fmaxf(m, v[l]);
            float sum = 0.f;
#pragma unroll
            for (int l = 0; l < LL; l++) { v[l] = __expf(v[l] - m); sum += v[l]; }
            float r = 1.f / sum;
            float* op = out + (size_t)slot * LL;
#pragma unroll
            for (int l = 0; l < LL; l++) op[l] = v[l] * r;
        }
        __syncwarp();   // protect sitem before next iteration
    }

    // ---- tail fill: invalid dest slots get softmax(bias) constant ----
    int n_tail = BB * SS - total;
    if (n_tail > 0) {
        float bv[LL];
#pragma unroll
        for (int l = 0; l < LL; l++) bv[l] = Bs[l];
        float mx = bv[0];
#pragma unroll
        for (int l = 1; l < LL; l++) mx = fmaxf(mx, bv[l]);
        float sum = 0.f;
#pragma unroll
        for (int l = 0; l < LL; l++) { bv[l] = __expf(bv[l] - mx); sum += bv[l]; }
        float r = 1.f / sum;
#pragma unroll
        for (int l = 0; l < LL; l++) bv[l] *= r;

        int gtid = blockIdx.x * 256 + tid;
        int gsz = NBLK * 256;
        for (int j = gtid; j < n_tail; j += gsz) {
            // largest b with tpref(b) = b*SS - pref[b] <= j
            int b = 0;
#pragma unroll
            for (int st = 32; st >= 1; st >>= 1) {
                int m = b + st;
                if (m <= BB - 1 && (m * SS - pref[m]) <= j) b = m;
            }
            int d = (pref[b + 1] - pref[b]) + (j - (b * SS - pref[b]));
            float* op = out + (size_t)(b * SS + d) * LL;
#pragma unroll
            for (int l = 0; l < LL; l++) op[l] = bv[l];
        }
    }
}

// ---------------------------------------------------------------------------
extern "C" void kernel_launch(void* const* d_in, const int* in_sizes, int n_in,
                              void* d_out, int out_size) {
    const float* seq  = (const float*)d_in[0];   // [64,512,768] f32
    const int*   mask = (const int*)d_in[1];     // [64,512] i32
    const float* W    = (const float*)d_in[2];   // [768,9] f32
    const float* bias = (const float*)d_in[3];   // [9] f32
    float* out = (float*)d_out;                  // [64,512,9] f32

    scan_kernel<<<2, 1024>>>(mask);
    main_kernel<<<NBLK, 256>>>(seq, W, bias, out);
}